// round 15
// baseline (speedup 1.0000x reference)
#include <cuda_runtime.h>
#include <cuda_fp16.h>
#include <math_constants.h>
#include <cstdint>

#define Nn   16384
#define Cc   64
#define KNN  16
#define Rr   4
#define CR   256              // C*R
#define RI   8                // rows per ag block
#define IB   64               // i-rows per knn CTA
#define TJ   128              // j-tile
#define NT   (Nn / TJ)        // 128 tiles
#define CAND 64               // candidates per row (4 stripes x 16)
#define BIAS 256.0f           // distance bias: keeps d positive -> asuint monotonic

// ---- scratch (device globals; no allocation allowed) ----
__device__ float g_A[Nn * CR];       // x @ (W1 - W2) + b
__device__ float g_G[Nn * CR];       // x @ W2
__device__ float g_sqb[Nn];          // row squared norms + BIAS
__device__ uint2 g_xh[Nn * 16];      // fp16 hi fragment-packed (2 MB)
__device__ int   g_ci[Nn * CAND];    // candidate indices (4 MB)
__device__ int   g_idx[Nn * KNN];    // final knn indices

// ---- smem map (bytes) for pass-1 knn kernel ----
#define SM_B    0                         // 2 x 2048 uint2 = 32768
#define SM_SQJ  32768                     // 2 x 128 floats = 1024
#define SM_TOT  33792

__device__ __forceinline__ uint32_t smem_u32(const void* p) {
    uint32_t a;
    asm("{ .reg .u64 t; cvta.to.shared.u64 t, %1; cvt.u32.u64 %0, t; }" : "=r"(a) : "l"(p));
    return a;
}

__device__ __forceinline__ void mma_f16(float* c, const uint32_t* a,
                                        uint32_t b0, uint32_t b1) {
    asm volatile(
        "mma.sync.aligned.m16n8k16.row.col.f32.f16.f16.f32 "
        "{%0,%1,%2,%3}, {%4,%5,%6,%7}, {%8,%9}, {%0,%1,%2,%3};"
        : "+f"(c[0]), "+f"(c[1]), "+f"(c[2]), "+f"(c[3])
        : "r"(a[0]), "r"(a[1]), "r"(a[2]), "r"(a[3]), "r"(b0), "r"(b1));
}

__device__ __forceinline__ void cpa16(uint32_t dst, const void* src) {
    asm volatile("cp.async.cg.shared.global [%0], [%1], 16;"
                 :: "r"(dst), "l"(__cvta_generic_to_global(src)));
}
__device__ __forceinline__ void cpa4(uint32_t dst, const void* src) {
    asm volatile("cp.async.ca.shared.global [%0], [%1], 4;"
                 :: "r"(dst), "l"(__cvta_generic_to_global(src)));
}

__device__ __forceinline__ uint32_t pack_h2(float a, float b) {  // a in low half
    __half2 h = __floats2half2_rn(a, b);
    return reinterpret_cast<uint32_t&>(h);
}

// Sorted-list half-insert. List ascending; caller guarantees key < kl[15].
// If key >= kl[7], only the upper 8 slots need the bubble pass.
__device__ __forceinline__ void kins16(uint32_t (&kl)[16], uint32_t key) {
    uint32_t c = key;
    if (key < kl[7]) {
        #pragma unroll
        for (int p = 0; p < 8; p++) {
            const uint32_t lo = min(c, kl[p]);
            c = max(c, kl[p]);
            kl[p] = lo;
        }
    }
    #pragma unroll
    for (int p = 8; p < 16; p++) {
        const uint32_t lo = min(c, kl[p]);
        c = max(c, kl[p]);
        kl[p] = lo;
    }
}

// ---------------------------------------------------------------------------
// sq precompute (slot 1): g_sqb[i] = |x_i|^2 + BIAS
// ---------------------------------------------------------------------------
__global__ __launch_bounds__(256) void sq_kernel(const float* __restrict__ x) {
    const int i = blockIdx.x * 256 + threadIdx.x;
    const float4* __restrict__ x4 = (const float4*)x;
    float s = 0.f;
    #pragma unroll
    for (int c = 0; c < 16; c++) {
        const float4 v = x4[i * 16 + c];
        s = fmaf(v.x, v.x, s); s = fmaf(v.y, v.y, s);
        s = fmaf(v.z, v.z, s); s = fmaf(v.w, v.w, s);
    }
    g_sqb[i] = s + BIAS;
}

// ---------------------------------------------------------------------------
// Fragment pack (slot 2; mapping validated R5/R8/R9): slot s -> octet o = s>>7,
// q = (s>>5)&3, lane = s&31 (g = lane>>2, t = lane&3); row j = o*8+g,
// cols c = q*16 + 2t (+1, +8, +9). uint2 = (w0hi, w1hi).
// ---------------------------------------------------------------------------
__global__ __launch_bounds__(256) void xf_kernel(const float* __restrict__ x) {
    const int s    = blockIdx.x * 256 + threadIdx.x;  // < Nn*16
    const int lane = s & 31;
    const int q    = (s >> 5) & 3;
    const int o    = s >> 7;
    const int g = lane >> 2, t = lane & 3;
    const int j = o * 8 + g;
    const int c = q * 16 + 2 * t;

    uint2 out;
    out.x = pack_h2(x[j * Cc + c],     x[j * Cc + c + 1]);
    out.y = pack_h2(x[j * Cc + c + 8], x[j * Cc + c + 9]);
    g_xh[s] = out;
}

// ---------------------------------------------------------------------------
// A/G precompute (slot 3): block = 8 rows, 256 threads
// ---------------------------------------------------------------------------
__global__ __launch_bounds__(256) void ag_kernel(const float* __restrict__ x,
                                                 const float* __restrict__ W,
                                                 const float* __restrict__ b) {
    __shared__ float shx[RI * Cc];
    const int i0  = blockIdx.x * RI;
    const int tid = threadIdx.x;

    shx[tid]       = x[i0 * Cc + tid];
    shx[tid + 256] = x[i0 * Cc + tid + 256];
    __syncthreads();

    float aacc[RI], gacc[RI];
    const float bb = b[tid];
    #pragma unroll
    for (int r = 0; r < RI; r++) { aacc[r] = bb; gacc[r] = 0.f; }

    #pragma unroll 4
    for (int c = 0; c < Cc; c++) {
        const float w1 = W[c * CR + tid];
        const float w2 = W[(c + Cc) * CR + tid];
        const float wd = w1 - w2;
        #pragma unroll
        for (int r = 0; r < RI; r++) {
            const float xv = shx[r * Cc + c];
            aacc[r] = fmaf(xv, wd, aacc[r]);
            gacc[r] = fmaf(xv, w2, gacc[r]);
        }
    }
    #pragma unroll
    for (int r = 0; r < RI; r++) {
        g_A[(i0 + r) * CR + tid] = aacc[r];
        g_G[(i0 + r) * CR + tid] = gacc[r];
    }
}

// ---------------------------------------------------------------------------
// Pass 1 (slot 4): approximate KNN, fp16 hi.hi mma.sync, sorted packed-key
// register top-16 with half-insert. CTA = 64 i-rows (4 warps x 16), 128 thr,
// grid 256, tiles of 128 j, double-buffered cp.async B.
// Thread (g,t) of warp w: rows (w*16+g, +8); stripe t covers j%8 in {2t,2t+1}.
// key = (asuint(sqb_j - 2*dot) & 0xFFFFC000) | j   (positive, monotonic).
// ---------------------------------------------------------------------------
__global__ __launch_bounds__(128, 2) void knn_pass1_kernel() {
    extern __shared__ char smem[];
    const uint32_t sb  = smem_u32(smem);
    const uint2* sB    = (const uint2*)smem;             // [2][2048]
    const float* sqjs  = (const float*)(smem + SM_SQJ);  // [2][128]

    const int tid  = threadIdx.x;
    const int w    = tid >> 5;
    const int lane = tid & 31;
    const int t_   = lane & 3;
    const int bid  = blockIdx.x;
    const int i0   = bid * IB;
    const int ig0  = i0 + w * 16 + (lane >> 2);
    const int ig1  = ig0 + 8;

    // ---- A fragments (hi only): rows i0 + w*16 .. +15 = octets oA, oA+1 ----
    uint32_t Ah[16];   // [q][4]
    {
        const int oA = bid * 8 + w * 2;
        #pragma unroll
        for (int q = 0; q < 4; q++) {
            const uint2 ua = g_xh[(oA * 4 + q) * 32 + lane];
            const uint2 ub = g_xh[((oA + 1) * 4 + q) * 32 + lane];
            Ah[q * 4 + 0] = ua.x; Ah[q * 4 + 1] = ub.x;
            Ah[q * 4 + 2] = ua.y; Ah[q * 4 + 3] = ub.y;
        }
    }

    // ---- sorted packed-key top-16 lists in registers ----
    uint32_t kl0[16], kl1[16];
    #pragma unroll
    for (int p = 0; p < KNN; p++) { kl0[p] = 0xFFFFFFFFu; kl1[p] = 0xFFFFFFFFu; }

    // ---- tile fill: 2048 uint2 (16 KB) + 128 sqb ----
    auto fill = [&](int jt, int buf) {
        const uint32_t dstB = sb + SM_B + buf * 16384 + tid * 16;
        const uint4* src = (const uint4*)(g_xh + (size_t)jt * 2048) + tid;
        #pragma unroll
        for (int s = 0; s < 8; s++) cpa16(dstB + s * 2048, src + s * 128);
        cpa4(sb + SM_SQJ + buf * 512 + tid * 4, &g_sqb[jt * TJ + tid]);
    };

    fill(0, 0);
    asm volatile("cp.async.commit_group;" ::: "memory");
    asm volatile("cp.async.wait_group 0;" ::: "memory");
    __syncthreads();

    for (int tt = 0; tt < NT; tt++) {
        const int buf = tt & 1;
        if (tt + 1 < NT) {
            fill(tt + 1, buf ^ 1);
            asm volatile("cp.async.commit_group;" ::: "memory");
        }
        const uint2* Bb  = sB + buf * 2048;
        const float* sqj = sqjs + buf * TJ;
        const int jbase  = tt * TJ;

        #pragma unroll 4
        for (int ob = 0; ob < 16; ob++) {
            float ch[4] = {0.f, 0.f, 0.f, 0.f};
            #pragma unroll
            for (int q = 0; q < 4; q++) {
                const uint2 bv = Bb[(ob * 4 + q) * 32 + lane];
                mma_f16(ch, Ah + q * 4, bv.x, bv.y);   // hi . hi
            }
            const int jl = ob * 8 + 2 * t_;
            const int jg = jbase + jl;
            const float2 sq2 = *(const float2*)(sqj + jl);
            const float d00 = fmaf(ch[0], -2.0f, sq2.x);   // row g,   col jl
            const float d01 = fmaf(ch[1], -2.0f, sq2.y);   // row g,   col jl+1
            const float d10 = fmaf(ch[2], -2.0f, sq2.x);   // row g+8, col jl
            const float d11 = fmaf(ch[3], -2.0f, sq2.y);   // row g+8, col jl+1
            const uint32_t k00 = (__float_as_uint(d00) & 0xFFFFC000u) | (uint32_t)jg;
            const uint32_t k01 = (__float_as_uint(d01) & 0xFFFFC000u) | (uint32_t)(jg + 1);
            const uint32_t k10 = (__float_as_uint(d10) & 0xFFFFC000u) | (uint32_t)jg;
            const uint32_t k11 = (__float_as_uint(d11) & 0xFFFFC000u) | (uint32_t)(jg + 1);
            if (k00 < kl0[15]) kins16(kl0, k00);
            if (k01 < kl0[15]) kins16(kl0, k01);
            if (k10 < kl1[15]) kins16(kl1, k10);
            if (k11 < kl1[15]) kins16(kl1, k11);
        }

        asm volatile("cp.async.wait_group 0;" ::: "memory");
        __syncthreads();
    }

    // ---- write stripe candidate indices (low 14 bits of keys) ----
    #pragma unroll
    for (int p = 0; p < KNN; p++) {
        g_ci[ig0 * CAND + t_ * KNN + p] = (int)(kl0[p] & 0x3FFFu);
        g_ci[ig1 * CAND + t_ * KNN + p] = (int)(kl1[p] & 0x3FFFu);
    }
}

// ---------------------------------------------------------------------------
// Pass 2 (slot 5): exact fp32 refine of 64 candidates per row; warp per row.
// Batched gathers (16 loads in flight), redux-based 16-round selection.
// ---------------------------------------------------------------------------
__global__ __launch_bounds__(256) void refine_kernel(const float* __restrict__ x) {
    __shared__ float sxi[8 * Cc];
    const int tid  = threadIdx.x;
    const int w    = tid >> 5;
    const int lane = tid & 31;
    const int i    = blockIdx.x * 8 + w;

    ((float2*)sxi)[tid] = ((const float2*)(x + (size_t)blockIdx.x * 8 * Cc))[tid];
    __syncthreads();
    const float* xi = sxi + w * Cc;

    const int c0 = g_ci[i * CAND + lane];
    const int c1 = g_ci[i * CAND + 32 + lane];

    const float4* __restrict__ x4 = (const float4*)x;
    float dot0 = 0.f, dot1 = 0.f;
    #pragma unroll
    for (int h = 0; h < 2; h++) {
        float4 A[8], B[8];
        #pragma unroll
        for (int c = 0; c < 8; c++) {
            A[c] = x4[c0 * 16 + h * 8 + c];
            B[c] = x4[c1 * 16 + h * 8 + c];
        }
        #pragma unroll
        for (int c = 0; c < 8; c++) {
            const int cb = (h * 8 + c) * 4;
            const float x0 = xi[cb], x1 = xi[cb + 1], x2 = xi[cb + 2], x3 = xi[cb + 3];
            dot0 = fmaf(x0, A[c].x, dot0); dot0 = fmaf(x1, A[c].y, dot0);
            dot0 = fmaf(x2, A[c].z, dot0); dot0 = fmaf(x3, A[c].w, dot0);
            dot1 = fmaf(x0, B[c].x, dot1); dot1 = fmaf(x1, B[c].y, dot1);
            dot1 = fmaf(x2, B[c].z, dot1); dot1 = fmaf(x3, B[c].w, dot1);
        }
    }
    const float d0 = fmaf(dot0, -2.0f, g_sqb[c0]);   // positive (biased)
    const float d1 = fmaf(dot1, -2.0f, g_sqb[c1]);
    uint32_t k0 = (c0 == i) ? 0xFFFFFFFFu : __float_as_uint(d0);
    uint32_t k1 = (c1 == i) ? 0xFFFFFFFFu : __float_as_uint(d1);

    #pragma unroll
    for (int r = 0; r < KNN; r++) {
        const uint32_t m = min(k0, k1);
        const uint32_t g = __reduce_min_sync(0xFFFFFFFFu, m);
        const bool h0 = (k0 == g);
        const bool h1 = (k1 == g);
        const uint32_t bal = __ballot_sync(0xFFFFFFFFu, h0 | h1);
        const int src = __ffs(bal) - 1;
        const int jj  = __shfl_sync(0xFFFFFFFFu, h0 ? c0 : c1, src);
        if (lane == 0) g_idx[i * KNN + r] = jj;
        if (lane == src) { if (h0) k0 = 0xFFFFFFFFu; else k1 = 0xFFFFFFFFu; }
    }
}

// ---------------------------------------------------------------------------
// Output (slot 6): out[i] = relu(max_k (A_i + G_{idx[i,k]})), (C,R)->(R,C)
// ---------------------------------------------------------------------------
__global__ __launch_bounds__(CR) void out_kernel(float* __restrict__ out) {
    __shared__ int   sidx[KNN];
    __shared__ float sv[CR];
    const int i = blockIdx.x;
    const int o = threadIdx.x;
    if (o < KNN) sidx[o] = g_idx[i * KNN + o];
    __syncthreads();

    const float a = g_A[i * CR + o];
    float m = -CUDART_INF_F;
    #pragma unroll
    for (int k = 0; k < KNN; k++) {
        m = fmaxf(m, a + g_G[sidx[k] * CR + o]);
    }
    sv[o] = fmaxf(m, 0.f);
    __syncthreads();

    const int p = o;
    const int r = p >> 6;
    const int c = p & 63;
    out[i * CR + p] = sv[c * Rr + r];
}

// ---------------------------------------------------------------------------
extern "C" void kernel_launch(void* const* d_in, const int* in_sizes, int n_in,
                              void* d_out, int out_size) {
    const float* x = (const float*)d_in[0];
    const float* W = (const float*)d_in[1];
    const float* b = (const float*)d_in[2];
    float* out = (float*)d_out;

    sq_kernel<<<Nn / 256, 256>>>(x);           // slot 1
    xf_kernel<<<Nn * 16 / 256, 256>>>(x);      // slot 2
    ag_kernel<<<Nn / RI, 256>>>(x, W, b);      // slot 3
    knn_pass1_kernel<<<Nn / IB, 128, SM_TOT>>>();  // slot 4 (ncu capture)
    refine_kernel<<<Nn / 8, 256>>>(x);         // slot 5
    out_kernel<<<Nn, CR>>>(out);               // slot 6
}